// round 9
// baseline (speedup 1.0000x reference)
#include <cuda_runtime.h>
#include <cuda_bf16.h>
#include <math_constants.h>

// Problem constants
#define NB 8          // batch
#define NY 180        // RENDER
#define NX 91         // XDIM+1
#define NV 192        // TEMPLATERES
#define SCALE_IN (32400.0f / 7077888.0f)   // RENDER^2 / TEMPLATERES^3

typedef unsigned long long ull;

// Scratch (device globals; no allocation allowed)
__device__ float2 g_tmid[NB * NY * NX];    // after column iDFT:  [b][ky][x]
__device__ ull    g_cand[NB * NY * 4];     // per-row top-4 packed keys
__device__ int    g_cnt[NB];               // last-block counters (reset in kernel A)

// ---- packed key helpers: (orderable float bits << 32) | ~index -------------
__device__ __forceinline__ unsigned f2ord(float v) {
    unsigned u = __float_as_uint(v);
    return (u & 0x80000000u) ? ~u : (u | 0x80000000u);
}
__device__ __forceinline__ float ord2f(unsigned ou) {
    unsigned u = (ou & 0x80000000u) ? (ou ^ 0x80000000u) : ~ou;
    return __uint_as_float(u);
}
__device__ __forceinline__ ull kmax(ull a, ull b) { return a > b ? a : b; }
__device__ __forceinline__ ull kmin(ull a, ull b) { return a < b ? a : b; }

// Branch-free merge of two desc-sorted 4-lists -> top-4.
__device__ __forceinline__ void merge4(ull& a0, ull& a1, ull& a2, ull& a3,
                                       ull b0, ull b1, ull b2, ull b3) {
    ull m0 = kmax(a0, b0);
    ull m1 = kmax(kmax(a1, b1), kmin(a0, b0));
    ull m2 = kmax(kmax(a2, b2), kmax(kmin(a0, b1), kmin(a1, b0)));
    ull m3 = kmax(kmax(a3, b3),
                  kmax(kmin(a1, b1), kmax(kmin(a0, b2), kmin(a2, b0))));
    a0 = m0; a1 = m1; a2 = m2; a3 = m3;
}

// ---------------------------------------------------------------------------
// Kernel A: block = (b, x) column. Thread t (=output row y, pre-fftshifted)
// rotates the grid point, trilinearly samples the volume (branchless zero-pad,
// MLP=16), multiplies by conj(ref) in registers, drops into smem, then the
// block performs the length-180 inverse DFT along y (2-way ILP).
// Also resets the last-block counters for kernel B.
// ---------------------------------------------------------------------------
__global__ __launch_bounds__(192) void kA_sample_ifft_y(
    const float* __restrict__ src,
    const float* __restrict__ rot,
    const float* __restrict__ ref)
{
    __shared__ float2 col[NY];
    __shared__ float2 tw[NY];

    int bx = blockIdx.x;          // 0 .. NB*NX-1
    int x  = bx % NX;
    int b  = bx / NX;
    int t  = threadIdx.x;         // 0..191

    if (bx == 0 && t < NB) g_cnt[t] = 0;   // reset counters for kernel B

    if (t < NY) {
        float s, c;
        sincospif((float)t * (1.0f / 90.0f), &s, &c);   // 2*pi*t/180
        tw[t] = make_float2(c, s);
    }

    if (t < NY) {
        int y = t;
        int g = y + 90; if (g >= 180) g -= 180;         // fftshift pre-map
        float gx = (float)x        * (1.0f / 96.0f);
        float gy = (float)(g - 90) * (1.0f / 96.0f);

        const float* R = rot + b * 9;
        float p0 = gx * R[0] + gy * R[3];
        float p1 = gx * R[1] + gy * R[4];
        float p2 = gx * R[2] + gy * R[5];

        float fx = (p0 + 1.0f) * 0.5f * 191.0f;
        float fy = (p1 + 1.0f) * 0.5f * 191.0f;
        float fz = (p2 + 1.0f) * 0.5f * 191.0f;
        float fx0 = floorf(fx), fy0 = floorf(fy), fz0 = floorf(fz);
        float wx = fx - fx0, wy = fy - fy0, wz = fz - fz0;
        int x0 = (int)fx0, y0 = (int)fy0, z0 = (int)fz0;

        // branchless zero-pad: clamp indices, mask weights
        int xc0 = min(max(x0, 0), NV - 1),     xc1 = min(max(x0 + 1, 0), NV - 1);
        int yc0 = min(max(y0, 0), NV - 1),     yc1 = min(max(y0 + 1, 0), NV - 1);
        int zc0 = min(max(z0, 0), NV - 1),     zc1 = min(max(z0 + 1, 0), NV - 1);
        float wx0 = (1.0f - wx) * (((unsigned)x0       < NV) ? 1.0f : 0.0f);
        float wx1 =         wx  * (((unsigned)(x0 + 1) < NV) ? 1.0f : 0.0f);
        float wy0 = (1.0f - wy) * (((unsigned)y0       < NV) ? 1.0f : 0.0f);
        float wy1 =         wy  * (((unsigned)(y0 + 1) < NV) ? 1.0f : 0.0f);
        float wz0 = (1.0f - wz) * (((unsigned)z0       < NV) ? 1.0f : 0.0f);
        float wz1 =         wz  * (((unsigned)(z0 + 1) < NV) ? 1.0f : 0.0f);

        const float* vr = src + (size_t)b * 2 * NV * NV * NV;
        const float* vi = vr + (size_t)NV * NV * NV;

        size_t r00 = ((size_t)zc0 * NV + yc0) * NV;
        size_t r01 = ((size_t)zc0 * NV + yc1) * NV;
        size_t r10 = ((size_t)zc1 * NV + yc0) * NV;
        size_t r11 = ((size_t)zc1 * NV + yc1) * NV;

        float w000 = wz0 * wy0 * wx0, w001 = wz0 * wy0 * wx1;
        float w010 = wz0 * wy1 * wx0, w011 = wz0 * wy1 * wx1;
        float w100 = wz1 * wy0 * wx0, w101 = wz1 * wy0 * wx1;
        float w110 = wz1 * wy1 * wx0, w111 = wz1 * wy1 * wx1;

        // 16 independent loads — full MLP
        float a000 = __ldg(vr + r00 + xc0), a001 = __ldg(vr + r00 + xc1);
        float a010 = __ldg(vr + r01 + xc0), a011 = __ldg(vr + r01 + xc1);
        float a100 = __ldg(vr + r10 + xc0), a101 = __ldg(vr + r10 + xc1);
        float a110 = __ldg(vr + r11 + xc0), a111 = __ldg(vr + r11 + xc1);
        float b000 = __ldg(vi + r00 + xc0), b001 = __ldg(vi + r00 + xc1);
        float b010 = __ldg(vi + r01 + xc0), b011 = __ldg(vi + r01 + xc1);
        float b100 = __ldg(vi + r10 + xc0), b101 = __ldg(vi + r10 + xc1);
        float b110 = __ldg(vi + r11 + xc0), b111 = __ldg(vi + r11 + xc1);

        float re = w000 * a000 + w001 * a001 + w010 * a010 + w011 * a011
                 + w100 * a100 + w101 * a101 + w110 * a110 + w111 * a111;
        float im = w000 * b000 + w001 * b001 + w010 * b010 + w011 * b011
                 + w100 * b100 + w101 * b101 + w110 * b110 + w111 * b111;
        re *= SCALE_IN;
        im *= SCALE_IN;

        const float* rp = ref + ((size_t)(b * NY + y) * NX + x) * 2;
        float rr = rp[0], ri = rp[1];
        col[y] = make_float2(re * rr + im * ri, im * rr - re * ri);
    }
    __syncthreads();

    if (t < NY) {
        int ky = t;
        float ar0 = 0.0f, ai0 = 0.0f, ar1 = 0.0f, ai1 = 0.0f;
        int step2 = 2 * ky; if (step2 >= NY) step2 -= NY;
        int idx0 = 0, idx1 = ky;
        for (int y = 0; y < NY; y += 2) {
            float2 c0 = col[y];     float2 w0 = tw[idx0];
            float2 c1 = col[y + 1]; float2 w1 = tw[idx1];
            ar0 += c0.x * w0.x - c0.y * w0.y;
            ai0 += c0.x * w0.y + c0.y * w0.x;
            ar1 += c1.x * w1.x - c1.y * w1.y;
            ai1 += c1.x * w1.y + c1.y * w1.x;
            idx0 += step2; if (idx0 >= NY) idx0 -= NY;
            idx1 += step2; if (idx1 >= NY) idx1 -= NY;
        }
        g_tmid[(b * NY + ky) * NX + x] = make_float2(ar0 + ar1, ai0 + ai1);
    }
}

// ---------------------------------------------------------------------------
// Kernel B: block = (b, ky) row. c2r inverse DFT along x (91 -> 180, 2-way
// ILP), fused per-row top-4, then the LAST block of each batch merges all
// 720 candidates and writes the final output.
// Output layout: [0,32) r_k_val (8,4); [32,96) trans (8,4,2).
// ---------------------------------------------------------------------------
__global__ __launch_bounds__(192) void kB_c2r_top4_final(float* __restrict__ out)
{
    __shared__ float2 row[NX];
    __shared__ float2 tw[NY];
    __shared__ ull    wtop[6][4];
    __shared__ int    s_last;

    int bx = blockIdx.x;          // 0 .. NB*NY-1
    int ky = bx % NY;
    int b  = bx / NY;
    int t  = threadIdx.x;         // 0..191

    if (t < NY) {
        float s, c;
        sincospif((float)t * (1.0f / 90.0f), &s, &c);
        tw[t] = make_float2(c, s);
    }
    if (t < NX) row[t] = g_tmid[(b * NY + ky) * NX + t];
    __syncthreads();

    ull key = 0;                  // neutral
    if (t < NY) {
        int m = t;
        float acc = row[0].x + ((m & 1) ? -row[90].x : row[90].x);
        int step = 2 * m; if (step >= NY) step -= NY;
        float so = 0.0f, se = 0.0f;
        int idxo = m;             // k=1
        int idxe = step;          // k=2
        for (int k = 1; k < 90; k += 2) {       // odd k: 1..89 (45 terms)
            float2 w = tw[idxo]; float2 c = row[k];
            so += c.x * w.x - c.y * w.y;
            idxo += step; if (idxo >= NY) idxo -= NY;
        }
        for (int k = 2; k < 90; k += 2) {       // even k: 2..88 (44 terms)
            float2 w = tw[idxe]; float2 c = row[k];
            se += c.x * w.x - c.y * w.y;
            idxe += step; if (idxe >= NY) idxe -= NY;
        }
        acc += 2.0f * (so + se);
        float val = acc * (2.0f / 32400.0f);    // 2 (r_k_val) / 180^2 (irfft2)
        unsigned gi = (unsigned)(ky * NY + m);
        key = ((ull)f2ord(val) << 32) | (unsigned)(~gi);
    }

    // warp-level top-4
    ull a0 = key, a1 = 0, a2 = 0, a3 = 0;
#pragma unroll
    for (int s = 16; s > 0; s >>= 1) {
        ull b0 = __shfl_xor_sync(0xFFFFFFFFu, a0, s);
        ull b1 = __shfl_xor_sync(0xFFFFFFFFu, a1, s);
        ull b2 = __shfl_xor_sync(0xFFFFFFFFu, a2, s);
        ull b3 = __shfl_xor_sync(0xFFFFFFFFu, a3, s);
        merge4(a0, a1, a2, a3, b0, b1, b2, b3);
    }
    int wid = t >> 5, lane = t & 31;
    if (lane == 0) { wtop[wid][0] = a0; wtop[wid][1] = a1; wtop[wid][2] = a2; wtop[wid][3] = a3; }
    __syncthreads();

    if (t == 0) {
        ull r0 = wtop[0][0], r1 = wtop[0][1], r2 = wtop[0][2], r3 = wtop[0][3];
#pragma unroll
        for (int w = 1; w < 6; w++)
            merge4(r0, r1, r2, r3, wtop[w][0], wtop[w][1], wtop[w][2], wtop[w][3]);
        ull* c = g_cand + (size_t)(b * NY + ky) * 4;
        c[0] = r0; c[1] = r1; c[2] = r2; c[3] = r3;
        __threadfence();
        int prev = atomicAdd(&g_cnt[b], 1);
        s_last = (prev == NY - 1);
    }
    __syncthreads();

    // Last block of this batch: merge all 180*4 candidates -> output.
    if (s_last) {
        __threadfence();          // acquire: make all g_cand writes visible
        const ull* cand = g_cand + (size_t)b * NY * 4;
        ull c0 = 0, c1 = 0, c2 = 0, c3 = 0;
#pragma unroll
        for (int j = 0; j < 4; j++) {
            int i = t + j * 192;
            ull x = (i < NY * 4) ? cand[i] : 0;
            merge4(c0, c1, c2, c3, x, 0, 0, 0);
        }
#pragma unroll
        for (int s = 16; s > 0; s >>= 1) {
            ull b0 = __shfl_xor_sync(0xFFFFFFFFu, c0, s);
            ull b1 = __shfl_xor_sync(0xFFFFFFFFu, c1, s);
            ull b2 = __shfl_xor_sync(0xFFFFFFFFu, c2, s);
            ull b3 = __shfl_xor_sync(0xFFFFFFFFu, c3, s);
            merge4(c0, c1, c2, c3, b0, b1, b2, b3);
        }
        __syncthreads();          // wtop reuse safe
        if (lane == 0) { wtop[wid][0] = c0; wtop[wid][1] = c1; wtop[wid][2] = c2; wtop[wid][3] = c3; }
        __syncthreads();
        if (t == 0) {
            ull r0 = wtop[0][0], r1 = wtop[0][1], r2 = wtop[0][2], r3 = wtop[0][3];
#pragma unroll
            for (int w = 1; w < 6; w++)
                merge4(r0, r1, r2, r3, wtop[w][0], wtop[w][1], wtop[w][2], wtop[w][3]);
            ull rs[4] = { r0, r1, r2, r3 };
#pragma unroll
            for (int k = 0; k < 4; k++) {
                ull kk = rs[k];
                float v = ord2f((unsigned)(kk >> 32));
                unsigned gi = ~((unsigned)(kk & 0xFFFFFFFFu));
                int m  = (int)(gi % NY);
                int yy = (int)(gi / NY);
                out[b * 4 + k] = v;
                out[32 + (b * 4 + k) * 2 + 0] = (float)(m  - 90);
                out[32 + (b * 4 + k) * 2 + 1] = (float)(yy - 90);
            }
        }
    }
}

// ---------------------------------------------------------------------------
extern "C" void kernel_launch(void* const* d_in, const int* in_sizes, int n_in,
                              void* d_out, int out_size)
{
    // Positional defaults per metadata order: src, rot, ref_fft, gridF
    const float* src = (const float*)d_in[0];   // 8*2*192^3 = 113246208
    const float* rot = (n_in > 1) ? (const float*)d_in[1] : nullptr;  // 72
    const float* ref = (n_in > 2) ? (const float*)d_in[2] : nullptr;  // 262080
    for (int i = 0; i < n_in; i++) {
        switch (in_sizes[i]) {
            case 113246208: src = (const float*)d_in[i]; break;
            case 72:        rot = (const float*)d_in[i]; break;
            case 262080:    ref = (const float*)d_in[i]; break;
            default: break; // gridF unused — recomputed analytically
        }
    }
    float* out = (float*)d_out;

    kA_sample_ifft_y<<<NB * NX, 192>>>(src, rot, ref);
    kB_c2r_top4_final<<<NB * NY, 192>>>(out);
}

// round 10
// speedup vs baseline: 1.4129x; 1.4129x over previous
#include <cuda_runtime.h>
#include <cuda_bf16.h>
#include <math_constants.h>

// Problem constants
#define NB 8          // batch
#define NY 180        // RENDER
#define NX 91         // XDIM+1
#define NV 192        // TEMPLATERES
#define SCALE_IN (32400.0f / 7077888.0f)   // RENDER^2 / TEMPLATERES^3

typedef unsigned long long ull;

// Scratch (device globals; no allocation allowed)
__device__ float2 g_tmid[NB * NY * NX];    // after column iDFT:  [b][ky][x]
__device__ ull    g_cand[NB * NY * 4];     // per-row top-4 packed keys
__device__ int    g_cnt[NB];               // last-block counters (reset in kernel A)

// ---- packed key helpers: (orderable float bits << 32) | ~index -------------
__device__ __forceinline__ unsigned f2ord(float v) {
    unsigned u = __float_as_uint(v);
    return (u & 0x80000000u) ? ~u : (u | 0x80000000u);
}
__device__ __forceinline__ float ord2f(unsigned ou) {
    unsigned u = (ou & 0x80000000u) ? (ou ^ 0x80000000u) : ~ou;
    return __uint_as_float(u);
}
__device__ __forceinline__ ull kmax(ull a, ull b) { return a > b ? a : b; }
__device__ __forceinline__ ull kmin(ull a, ull b) { return a < b ? a : b; }

// Branch-free merge of two desc-sorted 4-lists -> top-4.
__device__ __forceinline__ void merge4(ull& a0, ull& a1, ull& a2, ull& a3,
                                       ull b0, ull b1, ull b2, ull b3) {
    ull m0 = kmax(a0, b0);
    ull m1 = kmax(kmax(a1, b1), kmin(a0, b0));
    ull m2 = kmax(kmax(a2, b2), kmax(kmin(a0, b1), kmin(a1, b0)));
    ull m3 = kmax(kmax(a3, b3),
                  kmax(kmin(a1, b1), kmax(kmin(a0, b2), kmin(a2, b0))));
    a0 = m0; a1 = m1; a2 = m2; a3 = m3;
}

// complex rotate: w <- w * s
__device__ __forceinline__ void crot(float2& w, float2 s) {
    float tx = w.x * s.x - w.y * s.y;
    float ty = w.x * s.y + w.y * s.x;
    w.x = tx; w.y = ty;
}

// ---------------------------------------------------------------------------
// Kernel A: block = (b, x) column. Thread t (=output row y, pre-fftshifted)
// rotates the grid point, trilinearly samples the volume (branchless zero-pad,
// MLP=16), multiplies by conj(ref) in registers, drops into smem, then the
// block performs the length-180 inverse DFT along y using per-thread twiddle
// ROTATION RECURRENCE (no table, no index-wrap ALU, no LDS conflicts).
// ---------------------------------------------------------------------------
__global__ __launch_bounds__(192) void kA_sample_ifft_y(
    const float* __restrict__ src,
    const float* __restrict__ rot,
    const float* __restrict__ ref)
{
    __shared__ float2 col[NY];

    int bx = blockIdx.x;          // 0 .. NB*NX-1
    int x  = bx % NX;
    int b  = bx / NX;
    int t  = threadIdx.x;         // 0..191

    if (bx == 0 && t < NB) g_cnt[t] = 0;   // reset counters for kernel B

    if (t < NY) {
        int y = t;
        int g = y + 90; if (g >= 180) g -= 180;         // fftshift pre-map
        float gx = (float)x        * (1.0f / 96.0f);
        float gy = (float)(g - 90) * (1.0f / 96.0f);

        const float* R = rot + b * 9;
        float p0 = gx * R[0] + gy * R[3];
        float p1 = gx * R[1] + gy * R[4];
        float p2 = gx * R[2] + gy * R[5];

        float fx = (p0 + 1.0f) * 0.5f * 191.0f;
        float fy = (p1 + 1.0f) * 0.5f * 191.0f;
        float fz = (p2 + 1.0f) * 0.5f * 191.0f;
        float fx0 = floorf(fx), fy0 = floorf(fy), fz0 = floorf(fz);
        float wx = fx - fx0, wy = fy - fy0, wz = fz - fz0;
        int x0 = (int)fx0, y0 = (int)fy0, z0 = (int)fz0;

        // branchless zero-pad: clamp indices, mask weights
        int xc0 = min(max(x0, 0), NV - 1),     xc1 = min(max(x0 + 1, 0), NV - 1);
        int yc0 = min(max(y0, 0), NV - 1),     yc1 = min(max(y0 + 1, 0), NV - 1);
        int zc0 = min(max(z0, 0), NV - 1),     zc1 = min(max(z0 + 1, 0), NV - 1);
        float wx0 = (1.0f - wx) * (((unsigned)x0       < NV) ? 1.0f : 0.0f);
        float wx1 =         wx  * (((unsigned)(x0 + 1) < NV) ? 1.0f : 0.0f);
        float wy0 = (1.0f - wy) * (((unsigned)y0       < NV) ? 1.0f : 0.0f);
        float wy1 =         wy  * (((unsigned)(y0 + 1) < NV) ? 1.0f : 0.0f);
        float wz0 = (1.0f - wz) * (((unsigned)z0       < NV) ? 1.0f : 0.0f);
        float wz1 =         wz  * (((unsigned)(z0 + 1) < NV) ? 1.0f : 0.0f);

        const float* vr = src + (size_t)b * 2 * NV * NV * NV;
        const float* vi = vr + (size_t)NV * NV * NV;

        size_t r00 = ((size_t)zc0 * NV + yc0) * NV;
        size_t r01 = ((size_t)zc0 * NV + yc1) * NV;
        size_t r10 = ((size_t)zc1 * NV + yc0) * NV;
        size_t r11 = ((size_t)zc1 * NV + yc1) * NV;

        float w000 = wz0 * wy0 * wx0, w001 = wz0 * wy0 * wx1;
        float w010 = wz0 * wy1 * wx0, w011 = wz0 * wy1 * wx1;
        float w100 = wz1 * wy0 * wx0, w101 = wz1 * wy0 * wx1;
        float w110 = wz1 * wy1 * wx0, w111 = wz1 * wy1 * wx1;

        // 16 independent loads — full MLP
        float a000 = __ldg(vr + r00 + xc0), a001 = __ldg(vr + r00 + xc1);
        float a010 = __ldg(vr + r01 + xc0), a011 = __ldg(vr + r01 + xc1);
        float a100 = __ldg(vr + r10 + xc0), a101 = __ldg(vr + r10 + xc1);
        float a110 = __ldg(vr + r11 + xc0), a111 = __ldg(vr + r11 + xc1);
        float b000 = __ldg(vi + r00 + xc0), b001 = __ldg(vi + r00 + xc1);
        float b010 = __ldg(vi + r01 + xc0), b011 = __ldg(vi + r01 + xc1);
        float b100 = __ldg(vi + r10 + xc0), b101 = __ldg(vi + r10 + xc1);
        float b110 = __ldg(vi + r11 + xc0), b111 = __ldg(vi + r11 + xc1);

        float re = w000 * a000 + w001 * a001 + w010 * a010 + w011 * a011
                 + w100 * a100 + w101 * a101 + w110 * a110 + w111 * a111;
        float im = w000 * b000 + w001 * b001 + w010 * b010 + w011 * b011
                 + w100 * b100 + w101 * b101 + w110 * b110 + w111 * b111;
        re *= SCALE_IN;
        im *= SCALE_IN;

        const float* rp = ref + ((size_t)(b * NY + y) * NX + x) * 2;
        float rr = rp[0], ri = rp[1];
        col[y] = make_float2(re * rr + im * ri, im * rr - re * ri);
    }
    __syncthreads();

    if (t < NY) {
        int ky = t;
        // theta = 2*pi*ky/180; w1 = e^{i theta}; w2 = w1^2 (step for both chains)
        float s1, c1;
        sincospif((float)ky * (1.0f / 90.0f), &s1, &c1);
        float2 wo = make_float2(c1, s1);                       // odd chain @ y=1
        float2 ws = make_float2(c1 * c1 - s1 * s1, 2.0f * c1 * s1);  // step e^{i 2theta}
        float2 we = make_float2(1.0f, 0.0f);                   // even chain @ y=0

        float ar0 = 0.0f, ai0 = 0.0f, ar1 = 0.0f, ai1 = 0.0f;
        for (int y = 0; y < NY; y += 2) {
            float2 c0 = col[y];
            float2 c1v = col[y + 1];
            ar0 += c0.x * we.x - c0.y * we.y;
            ai0 += c0.x * we.y + c0.y * we.x;
            ar1 += c1v.x * wo.x - c1v.y * wo.y;
            ai1 += c1v.x * wo.y + c1v.y * wo.x;
            crot(we, ws);
            crot(wo, ws);
        }
        g_tmid[(b * NY + ky) * NX + x] = make_float2(ar0 + ar1, ai0 + ai1);
    }
}

// ---------------------------------------------------------------------------
// Kernel B: block = (b, ky) row. c2r inverse DFT along x (91 -> 180) via
// twiddle rotation recurrence, fused per-row top-4, then the LAST block of
// each batch merges all 720 candidates and writes the final output.
// Output layout: [0,32) r_k_val (8,4); [32,96) trans (8,4,2).
// ---------------------------------------------------------------------------
__global__ __launch_bounds__(192) void kB_c2r_top4_final(float* __restrict__ out)
{
    __shared__ float2 row[NX];
    __shared__ ull    wtop[6][4];
    __shared__ int    s_last;

    int bx = blockIdx.x;          // 0 .. NB*NY-1
    int ky = bx % NY;
    int b  = bx / NY;
    int t  = threadIdx.x;         // 0..191

    if (t < NX) row[t] = g_tmid[(b * NY + ky) * NX + t];
    __syncthreads();

    ull key = 0;                  // neutral
    if (t < NY) {
        int m = t;
        float acc = row[0].x + ((m & 1) ? -row[90].x : row[90].x);

        // theta = 2*pi*m/180
        float s1, c1;
        sincospif((float)m * (1.0f / 90.0f), &s1, &c1);
        float2 wo = make_float2(c1, s1);                       // k=1
        float2 ws = make_float2(c1 * c1 - s1 * s1, 2.0f * c1 * s1);  // e^{i 2theta}
        float2 we = ws;                                        // k=2

        float so = 0.0f, se = 0.0f;
        for (int k = 1; k < 89; k += 2) {      // pairs (1,2)..(87,88)
            float2 co = row[k];
            float2 ce = row[k + 1];
            so += co.x * wo.x - co.y * wo.y;
            se += ce.x * we.x - ce.y * we.y;
            crot(wo, ws);
            crot(we, ws);
        }
        {   // k = 89 (odd, last)
            float2 co = row[89];
            so += co.x * wo.x - co.y * wo.y;
        }
        acc += 2.0f * (so + se);
        float val = acc * (2.0f / 32400.0f);   // 2 (r_k_val) / 180^2 (irfft2)
        unsigned gi = (unsigned)(ky * NY + m);
        key = ((ull)f2ord(val) << 32) | (unsigned)(~gi);
    }

    // warp-level top-4
    ull a0 = key, a1 = 0, a2 = 0, a3 = 0;
#pragma unroll
    for (int s = 16; s > 0; s >>= 1) {
        ull b0 = __shfl_xor_sync(0xFFFFFFFFu, a0, s);
        ull b1 = __shfl_xor_sync(0xFFFFFFFFu, a1, s);
        ull b2 = __shfl_xor_sync(0xFFFFFFFFu, a2, s);
        ull b3 = __shfl_xor_sync(0xFFFFFFFFu, a3, s);
        merge4(a0, a1, a2, a3, b0, b1, b2, b3);
    }
    int wid = t >> 5, lane = t & 31;
    if (lane == 0) { wtop[wid][0] = a0; wtop[wid][1] = a1; wtop[wid][2] = a2; wtop[wid][3] = a3; }
    __syncthreads();

    if (t == 0) {
        ull r0 = wtop[0][0], r1 = wtop[0][1], r2 = wtop[0][2], r3 = wtop[0][3];
#pragma unroll
        for (int w = 1; w < 6; w++)
            merge4(r0, r1, r2, r3, wtop[w][0], wtop[w][1], wtop[w][2], wtop[w][3]);
        ull* c = g_cand + (size_t)(b * NY + ky) * 4;
        c[0] = r0; c[1] = r1; c[2] = r2; c[3] = r3;
        __threadfence();
        int prev = atomicAdd(&g_cnt[b], 1);
        s_last = (prev == NY - 1);
    }
    __syncthreads();

    // Last block of this batch: merge all 180*4 candidates -> output.
    if (s_last) {
        __threadfence();          // acquire: make all g_cand writes visible
        const ull* cand = g_cand + (size_t)b * NY * 4;
        ull c0 = 0, c1 = 0, c2 = 0, c3 = 0;
#pragma unroll
        for (int j = 0; j < 4; j++) {
            int i = t + j * 192;
            ull x = (i < NY * 4) ? cand[i] : 0;
            merge4(c0, c1, c2, c3, x, 0, 0, 0);
        }
#pragma unroll
        for (int s = 16; s > 0; s >>= 1) {
            ull b0 = __shfl_xor_sync(0xFFFFFFFFu, c0, s);
            ull b1 = __shfl_xor_sync(0xFFFFFFFFu, c1, s);
            ull b2 = __shfl_xor_sync(0xFFFFFFFFu, c2, s);
            ull b3 = __shfl_xor_sync(0xFFFFFFFFu, c3, s);
            merge4(c0, c1, c2, c3, b0, b1, b2, b3);
        }
        __syncthreads();          // wtop reuse safe
        if (lane == 0) { wtop[wid][0] = c0; wtop[wid][1] = c1; wtop[wid][2] = c2; wtop[wid][3] = c3; }
        __syncthreads();
        if (t == 0) {
            ull r0 = wtop[0][0], r1 = wtop[0][1], r2 = wtop[0][2], r3 = wtop[0][3];
#pragma unroll
            for (int w = 1; w < 6; w++)
                merge4(r0, r1, r2, r3, wtop[w][0], wtop[w][1], wtop[w][2], wtop[w][3]);
            ull rs[4] = { r0, r1, r2, r3 };
#pragma unroll
            for (int k = 0; k < 4; k++) {
                ull kk = rs[k];
                float v = ord2f((unsigned)(kk >> 32));
                unsigned gi = ~((unsigned)(kk & 0xFFFFFFFFu));
                int m  = (int)(gi % NY);
                int yy = (int)(gi / NY);
                out[b * 4 + k] = v;
                out[32 + (b * 4 + k) * 2 + 0] = (float)(m  - 90);
                out[32 + (b * 4 + k) * 2 + 1] = (float)(yy - 90);
            }
        }
    }
}

// ---------------------------------------------------------------------------
extern "C" void kernel_launch(void* const* d_in, const int* in_sizes, int n_in,
                              void* d_out, int out_size)
{
    // Positional defaults per metadata order: src, rot, ref_fft, gridF
    const float* src = (const float*)d_in[0];   // 8*2*192^3 = 113246208
    const float* rot = (n_in > 1) ? (const float*)d_in[1] : nullptr;  // 72
    const float* ref = (n_in > 2) ? (const float*)d_in[2] : nullptr;  // 262080
    for (int i = 0; i < n_in; i++) {
        switch (in_sizes[i]) {
            case 113246208: src = (const float*)d_in[i]; break;
            case 72:        rot = (const float*)d_in[i]; break;
            case 262080:    ref = (const float*)d_in[i]; break;
            default: break; // gridF unused — recomputed analytically
        }
    }
    float* out = (float*)d_out;

    kA_sample_ifft_y<<<NB * NX, 192>>>(src, rot, ref);
    kB_c2r_top4_final<<<NB * NY, 192>>>(out);
}

// round 11
// speedup vs baseline: 1.9211x; 1.3596x over previous
#include <cuda_runtime.h>
#include <cuda_bf16.h>
#include <math_constants.h>

// Problem constants
#define NB 8          // batch
#define NY 180        // RENDER
#define NX 91         // XDIM+1
#define NV 192        // TEMPLATERES
#define SCALE_IN  (32400.0f / 7077888.0f)  // RENDER^2 / TEMPLATERES^3
#define SCALE_OUT (2.0f / 32400.0f)        // 2 (r_k_val) / 180^2 (irfft2 norm)

#define CPB 4         // columns per block in kernel A
#define NCB 23        // ceil(NX / CPB)
#define RPB 4         // rows per block in kernel B
#define NRB 45        // NY / RPB

typedef unsigned long long ull;

// Scratch (device globals; no allocation allowed)
__device__ float2 g_tmid[NB * NY * NX];    // after column iDFT:  [b][ky][x]
__device__ ull    g_cand[NB * NRB * 4];    // per-block top-4 packed keys
__device__ int    g_cnt[NB];               // last-block counters (reset in kernel A)

// ---- packed key helpers: (orderable float bits << 32) | ~index -------------
__device__ __forceinline__ unsigned f2ord(float v) {
    unsigned u = __float_as_uint(v);
    return (u & 0x80000000u) ? ~u : (u | 0x80000000u);
}
__device__ __forceinline__ float ord2f(unsigned ou) {
    unsigned u = (ou & 0x80000000u) ? (ou ^ 0x80000000u) : ~ou;
    return __uint_as_float(u);
}
__device__ __forceinline__ ull kmax(ull a, ull b) { return a > b ? a : b; }
__device__ __forceinline__ ull kmin(ull a, ull b) { return a < b ? a : b; }

// Branch-free merge of two desc-sorted 4-lists -> top-4 (distinct keys).
__device__ __forceinline__ void merge4(ull& a0, ull& a1, ull& a2, ull& a3,
                                       ull b0, ull b1, ull b2, ull b3) {
    ull m0 = kmax(a0, b0);
    ull m1 = kmax(kmax(a1, b1), kmin(a0, b0));
    ull m2 = kmax(kmax(a2, b2), kmax(kmin(a0, b1), kmin(a1, b0)));
    ull m3 = kmax(kmax(a3, b3),
                  kmax(kmin(a1, b1), kmax(kmin(a0, b2), kmin(a2, b0))));
    a0 = m0; a1 = m1; a2 = m2; a3 = m3;
}
__device__ __forceinline__ void cswap(ull& a, ull& b) {
    ull hi = kmax(a, b), lo = kmin(a, b); a = hi; b = lo;
}

// complex rotate: w <- w * s
__device__ __forceinline__ void crot(float2& w, float2 s) {
    float tx = w.x * s.x - w.y * s.y;
    float ty = w.x * s.y + w.y * s.x;
    w.x = tx; w.y = ty;
}

// ---------------------------------------------------------------------------
// Kernel A: block = (b, 4 columns). Phase 1: 192 threads sample 4*180 grid
// points (rotate, trilinear, branchless zero-pad, * conj(ref)) into smem.
// Phase 2: 46 threads per column compute the length-180 inverse DFT along y,
// each producing FOUR outputs {ky, 180-ky, 90+ky, 90-ky} via even/odd x
// cos/sin partial sums (4x work reduction), twiddles by rotation recurrence.
// ---------------------------------------------------------------------------
__global__ __launch_bounds__(192) void kA_sample_ifft_y(
    const float* __restrict__ src,
    const float* __restrict__ rot,
    const float* __restrict__ ref)
{
    __shared__ float2 cols[CPB][NY];

    int bx = blockIdx.x;          // 0 .. NB*NCB-1
    int cb = bx % NCB;
    int b  = bx / NCB;
    int x0 = cb * CPB;
    int t  = threadIdx.x;         // 0..191

    if (bx == 0 && t < NB) g_cnt[t] = 0;   // reset counters for kernel B

    // ---- Phase 1: sampling ----
    for (int i = t; i < CPB * NY; i += 192) {
        int c = i / NY, y = i % NY;
        int x = x0 + c;
        if (x >= NX) continue;

        int g = y + 90; if (g >= 180) g -= 180;         // fftshift pre-map
        float gx = (float)x        * (1.0f / 96.0f);
        float gy = (float)(g - 90) * (1.0f / 96.0f);

        const float* R = rot + b * 9;
        float p0 = gx * R[0] + gy * R[3];
        float p1 = gx * R[1] + gy * R[4];
        float p2 = gx * R[2] + gy * R[5];

        float fx = (p0 + 1.0f) * 0.5f * 191.0f;
        float fy = (p1 + 1.0f) * 0.5f * 191.0f;
        float fz = (p2 + 1.0f) * 0.5f * 191.0f;
        float fx0 = floorf(fx), fy0 = floorf(fy), fz0 = floorf(fz);
        float wx = fx - fx0, wy = fy - fy0, wz = fz - fz0;
        int ix = (int)fx0, iy = (int)fy0, iz = (int)fz0;

        int xc0 = min(max(ix, 0), NV - 1),     xc1 = min(max(ix + 1, 0), NV - 1);
        int yc0 = min(max(iy, 0), NV - 1),     yc1 = min(max(iy + 1, 0), NV - 1);
        int zc0 = min(max(iz, 0), NV - 1),     zc1 = min(max(iz + 1, 0), NV - 1);
        float wx0 = (1.0f - wx) * (((unsigned)ix       < NV) ? 1.0f : 0.0f);
        float wx1 =         wx  * (((unsigned)(ix + 1) < NV) ? 1.0f : 0.0f);
        float wy0 = (1.0f - wy) * (((unsigned)iy       < NV) ? 1.0f : 0.0f);
        float wy1 =         wy  * (((unsigned)(iy + 1) < NV) ? 1.0f : 0.0f);
        float wz0 = (1.0f - wz) * (((unsigned)iz       < NV) ? 1.0f : 0.0f);
        float wz1 =         wz  * (((unsigned)(iz + 1) < NV) ? 1.0f : 0.0f);

        const float* vr = src + (size_t)b * 2 * NV * NV * NV;
        const float* vi = vr + (size_t)NV * NV * NV;

        size_t r00 = ((size_t)zc0 * NV + yc0) * NV;
        size_t r01 = ((size_t)zc0 * NV + yc1) * NV;
        size_t r10 = ((size_t)zc1 * NV + yc0) * NV;
        size_t r11 = ((size_t)zc1 * NV + yc1) * NV;

        float w000 = wz0 * wy0 * wx0, w001 = wz0 * wy0 * wx1;
        float w010 = wz0 * wy1 * wx0, w011 = wz0 * wy1 * wx1;
        float w100 = wz1 * wy0 * wx0, w101 = wz1 * wy0 * wx1;
        float w110 = wz1 * wy1 * wx0, w111 = wz1 * wy1 * wx1;

        float a000 = __ldg(vr + r00 + xc0), a001 = __ldg(vr + r00 + xc1);
        float a010 = __ldg(vr + r01 + xc0), a011 = __ldg(vr + r01 + xc1);
        float a100 = __ldg(vr + r10 + xc0), a101 = __ldg(vr + r10 + xc1);
        float a110 = __ldg(vr + r11 + xc0), a111 = __ldg(vr + r11 + xc1);
        float b000 = __ldg(vi + r00 + xc0), b001 = __ldg(vi + r00 + xc1);
        float b010 = __ldg(vi + r01 + xc0), b011 = __ldg(vi + r01 + xc1);
        float b100 = __ldg(vi + r10 + xc0), b101 = __ldg(vi + r10 + xc1);
        float b110 = __ldg(vi + r11 + xc0), b111 = __ldg(vi + r11 + xc1);

        float re = w000 * a000 + w001 * a001 + w010 * a010 + w011 * a011
                 + w100 * a100 + w101 * a101 + w110 * a110 + w111 * a111;
        float im = w000 * b000 + w001 * b001 + w010 * b010 + w011 * b011
                 + w100 * b100 + w101 * b101 + w110 * b110 + w111 * b111;
        re *= SCALE_IN;
        im *= SCALE_IN;

        const float* rp = ref + ((size_t)(b * NY + y) * NX + x) * 2;
        float rr = rp[0], ri = rp[1];
        cols[c][y] = make_float2(re * rr + im * ri, im * rr - re * ri);
    }
    __syncthreads();

    // ---- Phase 2: iDFT along y, 4 outputs per thread ----
    int c   = t / 48;
    int kyl = t % 48;
    int x   = x0 + c;
    if (kyl < 46 && x < NX) {
        int ky = kyl;
        float s1, c1;
        sincospif((float)ky * (1.0f / 90.0f), &s1, &c1);   // theta = 2*pi*ky/180
        float2 we = make_float2(1.0f, 0.0f);               // even-y chain @ y=0
        float2 wo = make_float2(c1, s1);                   // odd-y chain  @ y=1
        float2 ws = make_float2(c1 * c1 - s1 * s1, 2.0f * c1 * s1);  // e^{i2theta}

        float AeX = 0, AeY = 0, BeX = 0, BeY = 0;   // even y: cos sums / sin sums
        float AoX = 0, AoY = 0, BoX = 0, BoY = 0;   // odd y
        for (int y = 0; y < NY; y += 2) {
            float2 v0 = cols[c][y];
            float2 v1 = cols[c][y + 1];
            AeX += v0.x * we.x; AeY += v0.y * we.x;
            BeX += v0.x * we.y; BeY += v0.y * we.y;
            AoX += v1.x * wo.x; AoY += v1.y * wo.x;
            BoX += v1.x * wo.y; BoY += v1.y * wo.y;
            crot(we, ws);
            crot(wo, ws);
        }
        float AX = AeX + AoX, AY = AeY + AoY;
        float BX = BeX + BoX, BY = BeY + BoY;
        float DX = AeX - AoX, DY = AeY - AoY;       // even - odd
        float EX = BeX - BoX, EY = BeY - BoY;

        float2* base = g_tmid + (size_t)b * NY * NX + x;
        int i0 = ky;
        int i1 = (NY - ky) % NY;
        int i2 = 90 + ky;
        int i3 = 90 - ky;
        base[(size_t)i0 * NX] = make_float2(AX - BY,  BX + AY);   // out[ky]
        base[(size_t)i1 * NX] = make_float2(AX + BY,  AY - BX);   // out[180-ky]
        base[(size_t)i2 * NX] = make_float2(DX - EY,  EX + DY);   // out[90+ky]
        base[(size_t)i3 * NX] = make_float2(DX + EY,  DY - EX);   // out[90-ky]
    }
}

// ---------------------------------------------------------------------------
// Kernel B: block = (b, 4 rows). c2r inverse DFT along x (91 -> 180): each
// thread (46 per row) produces FOUR outputs {m, 180-m, 90+m, 90-m} from the
// even/odd-k cos/sin partial sums. Block-level top-4 -> g_cand; the LAST
// block of each batch merges 45*4 = 180 candidates and writes the output.
// Output layout: [0,32) r_k_val (8,4); [32,96) trans (8,4,2).
// ---------------------------------------------------------------------------
__global__ __launch_bounds__(192) void kB_c2r_top4_final(float* __restrict__ out)
{
    __shared__ float2 rows[RPB][NX];
    __shared__ ull    wtop[6][4];
    __shared__ int    s_last;

    int bx = blockIdx.x;          // 0 .. NB*NRB-1
    int rb = bx % NRB;
    int b  = bx / NRB;
    int t  = threadIdx.x;         // 0..191

    for (int i = t; i < RPB * NX; i += 192) {
        int r = i / NX, k = i % NX;
        rows[r][k] = g_tmid[(size_t)(b * NY + rb * RPB + r) * NX + k];
    }
    __syncthreads();

    int r  = t / 48;
    int ml = t % 48;
    ull k0 = 0, k1 = 0, k2 = 0, k3 = 0;   // this thread's candidate keys
    if (ml < 46) {
        int ky = rb * RPB + r;
        int m  = ml;
        float base = rows[r][0].x + ((m & 1) ? -rows[r][90].x : rows[r][90].x);

        float s1, c1;
        sincospif((float)m * (1.0f / 90.0f), &s1, &c1);    // theta = 2*pi*m/180
        float2 wo = make_float2(c1, s1);                   // k=1
        float2 ws = make_float2(c1 * c1 - s1 * s1, 2.0f * c1 * s1);  // e^{i2theta}
        float2 we = ws;                                    // k=2

        float Ae = 0, Be = 0, Ao = 0, Bo = 0;  // A = sum ar*cos, B = sum ai*sin
        for (int k = 1; k < 89; k += 2) {
            float2 co = rows[r][k];
            float2 ce = rows[r][k + 1];
            Ao += co.x * wo.x; Bo += co.y * wo.y;
            Ae += ce.x * we.x; Be += ce.y * we.y;
            crot(wo, ws);
            crot(we, ws);
        }
        {   // k = 89 tail (odd)
            float2 co = rows[r][89];
            Ao += co.x * wo.x; Bo += co.y * wo.y;
        }

        float vm   = (base + 2.0f * ((Ae - Be) + (Ao - Bo))) * SCALE_OUT;  // r[m]
        float v180 = (base + 2.0f * ((Ae + Be) + (Ao + Bo))) * SCALE_OUT;  // r[180-m]
        float v90p = (base + 2.0f * ((Ae - Be) - (Ao - Bo))) * SCALE_OUT;  // r[90+m]
        float v90m = (base + 2.0f * ((Ae + Be) - (Ao + Bo))) * SCALE_OUT;  // r[90-m]

        unsigned gbase = (unsigned)(ky * NY);
        unsigned i0 = gbase + (unsigned)m;
        unsigned i1 = gbase + (unsigned)((NY - m) % NY);
        unsigned i2 = gbase + (unsigned)(90 + m);
        unsigned i3 = gbase + (unsigned)(90 - m);
        k0 = ((ull)f2ord(vm)   << 32) | (unsigned)(~i0);
        k1 = ((ull)f2ord(v180) << 32) | (unsigned)(~i1);
        k2 = ((ull)f2ord(v90p) << 32) | (unsigned)(~i2);
        k3 = ((ull)f2ord(v90m) << 32) | (unsigned)(~i3);
        if (m == 0 || m == 45) { k1 = 0; k3 = 0; }   // drop duplicate indices
    }

    // sort this thread's 4 keys desc (5-comparator network)
    cswap(k0, k1); cswap(k2, k3); cswap(k0, k2); cswap(k1, k3); cswap(k1, k2);

    // warp-level top-4
    ull a0 = k0, a1 = k1, a2 = k2, a3 = k3;
#pragma unroll
    for (int s = 16; s > 0; s >>= 1) {
        ull b0 = __shfl_xor_sync(0xFFFFFFFFu, a0, s);
        ull b1 = __shfl_xor_sync(0xFFFFFFFFu, a1, s);
        ull b2 = __shfl_xor_sync(0xFFFFFFFFu, a2, s);
        ull b3 = __shfl_xor_sync(0xFFFFFFFFu, a3, s);
        merge4(a0, a1, a2, a3, b0, b1, b2, b3);
    }
    int wid = t >> 5, lane = t & 31;
    if (lane == 0) { wtop[wid][0] = a0; wtop[wid][1] = a1; wtop[wid][2] = a2; wtop[wid][3] = a3; }
    __syncthreads();

    if (t == 0) {
        ull r0 = wtop[0][0], r1 = wtop[0][1], r2 = wtop[0][2], r3 = wtop[0][3];
#pragma unroll
        for (int w = 1; w < 6; w++)
            merge4(r0, r1, r2, r3, wtop[w][0], wtop[w][1], wtop[w][2], wtop[w][3]);
        ull* c = g_cand + (size_t)(b * NRB + rb) * 4;
        c[0] = r0; c[1] = r1; c[2] = r2; c[3] = r3;
        __threadfence();
        int prev = atomicAdd(&g_cnt[b], 1);
        s_last = (prev == NRB - 1);
    }
    __syncthreads();

    // Last block of this batch: merge all 45*4 = 180 candidates -> output.
    if (s_last) {
        __threadfence();          // acquire: make all g_cand writes visible
        const ull* cand = g_cand + (size_t)b * NRB * 4;
        ull c0 = (t < NRB * 4) ? cand[t] : 0, c1 = 0, c2 = 0, c3 = 0;
#pragma unroll
        for (int s = 16; s > 0; s >>= 1) {
            ull b0 = __shfl_xor_sync(0xFFFFFFFFu, c0, s);
            ull b1 = __shfl_xor_sync(0xFFFFFFFFu, c1, s);
            ull b2 = __shfl_xor_sync(0xFFFFFFFFu, c2, s);
            ull b3 = __shfl_xor_sync(0xFFFFFFFFu, c3, s);
            merge4(c0, c1, c2, c3, b0, b1, b2, b3);
        }
        __syncthreads();          // wtop reuse safe
        if (lane == 0) { wtop[wid][0] = c0; wtop[wid][1] = c1; wtop[wid][2] = c2; wtop[wid][3] = c3; }
        __syncthreads();
        if (t == 0) {
            ull r0 = wtop[0][0], r1 = wtop[0][1], r2 = wtop[0][2], r3 = wtop[0][3];
#pragma unroll
            for (int w = 1; w < 6; w++)
                merge4(r0, r1, r2, r3, wtop[w][0], wtop[w][1], wtop[w][2], wtop[w][3]);
            ull rs[4] = { r0, r1, r2, r3 };
#pragma unroll
            for (int k = 0; k < 4; k++) {
                ull kk = rs[k];
                float v = ord2f((unsigned)(kk >> 32));
                unsigned gi = ~((unsigned)(kk & 0xFFFFFFFFu));
                int m  = (int)(gi % NY);
                int yy = (int)(gi / NY);
                out[b * 4 + k] = v;
                out[32 + (b * 4 + k) * 2 + 0] = (float)(m  - 90);
                out[32 + (b * 4 + k) * 2 + 1] = (float)(yy - 90);
            }
        }
    }
}

// ---------------------------------------------------------------------------
extern "C" void kernel_launch(void* const* d_in, const int* in_sizes, int n_in,
                              void* d_out, int out_size)
{
    // Positional defaults per metadata order: src, rot, ref_fft, gridF
    const float* src = (const float*)d_in[0];   // 8*2*192^3 = 113246208
    const float* rot = (n_in > 1) ? (const float*)d_in[1] : nullptr;  // 72
    const float* ref = (n_in > 2) ? (const float*)d_in[2] : nullptr;  // 262080
    for (int i = 0; i < n_in; i++) {
        switch (in_sizes[i]) {
            case 113246208: src = (const float*)d_in[i]; break;
            case 72:        rot = (const float*)d_in[i]; break;
            case 262080:    ref = (const float*)d_in[i]; break;
            default: break; // gridF unused — recomputed analytically
        }
    }
    float* out = (float*)d_out;

    kA_sample_ifft_y<<<NB * NCB, 192>>>(src, rot, ref);
    kB_c2r_top4_final<<<NB * NRB, 192>>>(out);
}

// round 13
// speedup vs baseline: 2.1058x; 1.0962x over previous
#include <cuda_runtime.h>
#include <cuda_bf16.h>
#include <math_constants.h>

// Problem constants
#define NB 8          // batch
#define NY 180        // RENDER
#define NX 91         // XDIM+1
#define NV 192        // TEMPLATERES
#define SCALE_IN  (32400.0f / 7077888.0f)  // RENDER^2 / TEMPLATERES^3
#define SCALE_OUT (2.0f / 32400.0f)        // 2 (r_k_val) / 180^2 (irfft2 norm)

#define CPB 2         // columns per block in kernel A
#define NCB 46        // ceil(NX / CPB)
#define RPB 2         // rows per block in kernel B
#define NRB 90        // NY / RPB

typedef unsigned long long ull;

// Scratch (device globals; no allocation allowed)
__device__ float2 g_tmid[NB * NY * NX];    // after column iDFT:  [b][ky][x]
__device__ ull    g_cand[NB * NRB * 4];    // per-block top-4 packed keys
__device__ int    g_cnt[NB];               // last-block counters (reset in kernel A)

// ---- packed key helpers: (orderable float bits << 32) | ~index -------------
__device__ __forceinline__ unsigned f2ord(float v) {
    unsigned u = __float_as_uint(v);
    return (u & 0x80000000u) ? ~u : (u | 0x80000000u);
}
__device__ __forceinline__ float ord2f(unsigned ou) {
    unsigned u = (ou & 0x80000000u) ? (ou ^ 0x80000000u) : ~ou;
    return __uint_as_float(u);
}
__device__ __forceinline__ ull kmax(ull a, ull b) { return a > b ? a : b; }
__device__ __forceinline__ ull kmin(ull a, ull b) { return a < b ? a : b; }

// Branch-free merge of two desc-sorted 4-lists -> top-4 (distinct keys).
__device__ __forceinline__ void merge4(ull& a0, ull& a1, ull& a2, ull& a3,
                                       ull b0, ull b1, ull b2, ull b3) {
    ull m0 = kmax(a0, b0);
    ull m1 = kmax(kmax(a1, b1), kmin(a0, b0));
    ull m2 = kmax(kmax(a2, b2), kmax(kmin(a0, b1), kmin(a1, b0)));
    ull m3 = kmax(kmax(a3, b3),
                  kmax(kmin(a1, b1), kmax(kmin(a0, b2), kmin(a2, b0))));
    a0 = m0; a1 = m1; a2 = m2; a3 = m3;
}
__device__ __forceinline__ void cswap(ull& a, ull& b) {
    ull hi = kmax(a, b), lo = kmin(a, b); a = hi; b = lo;
}

// complex rotate: w <- w * s
__device__ __forceinline__ void crot(float2& w, float2 s) {
    float tx = w.x * s.x - w.y * s.y;
    float ty = w.x * s.y + w.y * s.x;
    w.x = tx; w.y = ty;
}

// ---------------------------------------------------------------------------
// Kernel A: block = (b, 2 columns). Phase 1: 192 threads sample 2*180 grid
// points into smem. Phase 2: per column, 46 outputs x 2 parity-threads:
// parity 0 = even-y chain, parity 1 = odd-y chain (45 iters each); partials
// exchanged with shfl_xor(1) executed UNCONDITIONALLY by all lanes (inactive
// lanes contribute zeros). parity 0 writes {ky, 180-ky}, parity 1 writes
// {90+ky, 90-ky} (skipped at ky=45 to avoid cross-thread duplicate writes).
// ---------------------------------------------------------------------------
__global__ __launch_bounds__(192) void kA_sample_ifft_y(
    const float* __restrict__ src,
    const float* __restrict__ rot,
    const float* __restrict__ ref)
{
    __shared__ float2 cols[CPB][NY];

    int bx = blockIdx.x;          // 0 .. NB*NCB-1
    int cb = bx % NCB;
    int b  = bx / NCB;
    int x0 = cb * CPB;
    int t  = threadIdx.x;         // 0..191

    if (bx == 0 && t < NB) g_cnt[t] = 0;   // reset counters for kernel B

    // ---- Phase 1: sampling ----
    for (int i = t; i < CPB * NY; i += 192) {
        int c = i / NY, y = i % NY;
        int x = x0 + c;
        if (x >= NX) continue;

        int g = y + 90; if (g >= 180) g -= 180;         // fftshift pre-map
        float gx = (float)x        * (1.0f / 96.0f);
        float gy = (float)(g - 90) * (1.0f / 96.0f);

        const float* R = rot + b * 9;
        float p0 = gx * R[0] + gy * R[3];
        float p1 = gx * R[1] + gy * R[4];
        float p2 = gx * R[2] + gy * R[5];

        float fx = (p0 + 1.0f) * 0.5f * 191.0f;
        float fy = (p1 + 1.0f) * 0.5f * 191.0f;
        float fz = (p2 + 1.0f) * 0.5f * 191.0f;
        float fx0 = floorf(fx), fy0 = floorf(fy), fz0 = floorf(fz);
        float wx = fx - fx0, wy = fy - fy0, wz = fz - fz0;
        int ix = (int)fx0, iy = (int)fy0, iz = (int)fz0;

        int xc0 = min(max(ix, 0), NV - 1),     xc1 = min(max(ix + 1, 0), NV - 1);
        int yc0 = min(max(iy, 0), NV - 1),     yc1 = min(max(iy + 1, 0), NV - 1);
        int zc0 = min(max(iz, 0), NV - 1),     zc1 = min(max(iz + 1, 0), NV - 1);
        float wx0 = (1.0f - wx) * (((unsigned)ix       < NV) ? 1.0f : 0.0f);
        float wx1 =         wx  * (((unsigned)(ix + 1) < NV) ? 1.0f : 0.0f);
        float wy0 = (1.0f - wy) * (((unsigned)iy       < NV) ? 1.0f : 0.0f);
        float wy1 =         wy  * (((unsigned)(iy + 1) < NV) ? 1.0f : 0.0f);
        float wz0 = (1.0f - wz) * (((unsigned)iz       < NV) ? 1.0f : 0.0f);
        float wz1 =         wz  * (((unsigned)(iz + 1) < NV) ? 1.0f : 0.0f);

        const float* vr = src + (size_t)b * 2 * NV * NV * NV;
        const float* vi = vr + (size_t)NV * NV * NV;

        size_t r00 = ((size_t)zc0 * NV + yc0) * NV;
        size_t r01 = ((size_t)zc0 * NV + yc1) * NV;
        size_t r10 = ((size_t)zc1 * NV + yc0) * NV;
        size_t r11 = ((size_t)zc1 * NV + yc1) * NV;

        float w000 = wz0 * wy0 * wx0, w001 = wz0 * wy0 * wx1;
        float w010 = wz0 * wy1 * wx0, w011 = wz0 * wy1 * wx1;
        float w100 = wz1 * wy0 * wx0, w101 = wz1 * wy0 * wx1;
        float w110 = wz1 * wy1 * wx0, w111 = wz1 * wy1 * wx1;

        float a000 = __ldg(vr + r00 + xc0), a001 = __ldg(vr + r00 + xc1);
        float a010 = __ldg(vr + r01 + xc0), a011 = __ldg(vr + r01 + xc1);
        float a100 = __ldg(vr + r10 + xc0), a101 = __ldg(vr + r10 + xc1);
        float a110 = __ldg(vr + r11 + xc0), a111 = __ldg(vr + r11 + xc1);
        float b000 = __ldg(vi + r00 + xc0), b001 = __ldg(vi + r00 + xc1);
        float b010 = __ldg(vi + r01 + xc0), b011 = __ldg(vi + r01 + xc1);
        float b100 = __ldg(vi + r10 + xc0), b101 = __ldg(vi + r10 + xc1);
        float b110 = __ldg(vi + r11 + xc0), b111 = __ldg(vi + r11 + xc1);

        float re = w000 * a000 + w001 * a001 + w010 * a010 + w011 * a011
                 + w100 * a100 + w101 * a101 + w110 * a110 + w111 * a111;
        float im = w000 * b000 + w001 * b001 + w010 * b010 + w011 * b011
                 + w100 * b100 + w101 * b101 + w110 * b110 + w111 * b111;
        re *= SCALE_IN;
        im *= SCALE_IN;

        const float* rp = ref + ((size_t)(b * NY + y) * NX + x) * 2;
        float rr = rp[0], ri = rp[1];
        cols[c][y] = make_float2(re * rr + im * ri, im * rr - re * ri);
    }
    __syncthreads();

    // ---- Phase 2: iDFT along y, parity-split chains ----
    int c      = t / 96;
    int u      = t % 96;
    int kyl    = u / 2;
    int parity = u & 1;
    int x      = x0 + c;
    bool active = (kyl < 46) && (x < NX);

    float AX = 0, AY = 0, BX = 0, BY = 0;   // cos sums / sin sums (this parity)
    if (active) {
        float s1, c1;
        sincospif((float)kyl * (1.0f / 90.0f), &s1, &c1);  // theta = 2*pi*ky/180
        float2 ws = make_float2(c1 * c1 - s1 * s1, 2.0f * c1 * s1);  // e^{i2theta}
        float2 w = parity ? make_float2(c1, s1) : make_float2(1.0f, 0.0f);
        for (int y = parity; y < NY; y += 2) {
            float2 v = cols[c][y];
            AX += v.x * w.x; AY += v.y * w.x;
            BX += v.x * w.y; BY += v.y * w.y;
            crot(w, ws);
        }
    }
    // UNCONDITIONAL exchange with partner lane (t^1) — all lanes participate
    float pAX = __shfl_xor_sync(0xFFFFFFFFu, AX, 1);
    float pAY = __shfl_xor_sync(0xFFFFFFFFu, AY, 1);
    float pBX = __shfl_xor_sync(0xFFFFFFFFu, BX, 1);
    float pBY = __shfl_xor_sync(0xFFFFFFFFu, BY, 1);

    if (active) {
        int ky = kyl;
        float2* base = g_tmid + (size_t)b * NY * NX + x;
        if (parity == 0) {
            // S = even + odd  (mine = even, partner = odd)
            float SX = AX + pAX, SY = AY + pAY;
            float TX = BX + pBX, TY = BY + pBY;
            int i0 = ky;
            int i1 = (NY - ky) % NY;
            base[(size_t)i0 * NX] = make_float2(SX - TY,  TX + SY);   // out[ky]
            base[(size_t)i1 * NX] = make_float2(SX + TY,  SY - TX);   // out[180-ky]
        } else if (ky != 45) {
            // D = even - odd  (mine = odd, partner = even)
            float DX = pAX - AX, DY = pAY - AY;
            float EX = pBX - BX, EY = pBY - BY;
            int i2 = 90 + ky;
            int i3 = 90 - ky;
            base[(size_t)i2 * NX] = make_float2(DX - EY,  EX + DY);   // out[90+ky]
            base[(size_t)i3 * NX] = make_float2(DX + EY,  DY - EX);   // out[90-ky]
        }
    }
}

// ---------------------------------------------------------------------------
// Kernel B: block = (b, 2 rows). c2r inverse DFT along x (91 -> 180) with
// parity-split k-chains: parity 0 = even k (44 iters), parity 1 = odd k
// (45 iters); partials exchanged with UNCONDITIONAL shfl_xor(1). parity 0
// emits candidates {m, 180-m}, parity 1 emits {90+m, 90-m}; duplicates
// dropped. Block top-4 -> g_cand; LAST block per batch merges 90*4 = 360.
// Output layout: [0,32) r_k_val (8,4); [32,96) trans (8,4,2).
// ---------------------------------------------------------------------------
__global__ __launch_bounds__(192) void kB_c2r_top4_final(float* __restrict__ out)
{
    __shared__ float2 rows[RPB][NX];
    __shared__ ull    wtop[6][4];
    __shared__ int    s_last;

    int bx = blockIdx.x;          // 0 .. NB*NRB-1
    int rb = bx % NRB;
    int b  = bx / NRB;
    int t  = threadIdx.x;         // 0..191

    for (int i = t; i < RPB * NX; i += 192) {
        int r = i / NX, k = i % NX;
        rows[r][k] = g_tmid[(size_t)(b * NY + rb * RPB + r) * NX + k];
    }
    __syncthreads();

    int r      = t / 96;
    int u      = t % 96;
    int ml     = u / 2;
    int parity = u & 1;
    bool active = (ml < 46);

    float A = 0, B = 0;           // A = sum ar*cos, B = sum ai*sin (this parity)
    if (active) {
        float s1, c1;
        sincospif((float)ml * (1.0f / 90.0f), &s1, &c1);   // theta = 2*pi*m/180
        float2 ws = make_float2(c1 * c1 - s1 * s1, 2.0f * c1 * s1);  // e^{i2theta}
        float2 w = parity ? make_float2(c1, s1) : ws;      // odd k=1 / even k=2
        int kstart = parity ? 1 : 2;
        for (int k = kstart; k < 90; k += 2) {
            float2 cv = rows[r][k];
            A += cv.x * w.x; B += cv.y * w.y;
            crot(w, ws);
        }
    }
    // UNCONDITIONAL exchange — all lanes participate
    float pA = __shfl_xor_sync(0xFFFFFFFFu, A, 1);
    float pB = __shfl_xor_sync(0xFFFFFFFFu, B, 1);

    ull k0 = 0, k1 = 0;           // this thread's candidate keys
    if (active) {
        int ky = rb * RPB + r;
        int m  = ml;
        float base = rows[r][0].x + ((m & 1) ? -rows[r][90].x : rows[r][90].x);
        unsigned gbase = (unsigned)(ky * NY);
        if (parity == 0) {
            // mine = even (Ae,Be), partner = odd (Ao,Bo)
            float vm   = (base + 2.0f * ((A - B) + (pA - pB))) * SCALE_OUT;  // r[m]
            float v180 = (base + 2.0f * ((A + B) + (pA + pB))) * SCALE_OUT;  // r[180-m]
            unsigned i0 = gbase + (unsigned)m;
            unsigned i1 = gbase + (unsigned)((NY - m) % NY);
            k0 = ((ull)f2ord(vm)   << 32) | (unsigned)(~i0);
            k1 = ((ull)f2ord(v180) << 32) | (unsigned)(~i1);
            if (m == 0) k1 = 0;                    // duplicate of i0
        } else if (m != 45) {
            // mine = odd (Ao,Bo), partner = even (Ae,Be)
            float v90p = (base + 2.0f * ((pA - pB) - (A - B))) * SCALE_OUT;  // r[90+m]
            float v90m = (base + 2.0f * ((pA + pB) - (A + B))) * SCALE_OUT;  // r[90-m]
            unsigned i2 = gbase + (unsigned)(90 + m);
            unsigned i3 = gbase + (unsigned)(90 - m);
            k0 = ((ull)f2ord(v90p) << 32) | (unsigned)(~i2);
            k1 = ((ull)f2ord(v90m) << 32) | (unsigned)(~i3);
            if (m == 0) k1 = 0;                    // i3=90 duplicate of i2
        }
        // m==45, parity==1: both indices duplicate parity 0's -> keys stay 0
    }

    cswap(k0, k1);                // desc order

    // warp-level top-4 (all lanes participate)
    ull a0 = k0, a1 = k1, a2 = 0, a3 = 0;
#pragma unroll
    for (int s = 16; s > 0; s >>= 1) {
        ull b0 = __shfl_xor_sync(0xFFFFFFFFu, a0, s);
        ull b1 = __shfl_xor_sync(0xFFFFFFFFu, a1, s);
        ull b2 = __shfl_xor_sync(0xFFFFFFFFu, a2, s);
        ull b3 = __shfl_xor_sync(0xFFFFFFFFu, a3, s);
        merge4(a0, a1, a2, a3, b0, b1, b2, b3);
    }
    int wid = t >> 5, lane = t & 31;
    if (lane == 0) { wtop[wid][0] = a0; wtop[wid][1] = a1; wtop[wid][2] = a2; wtop[wid][3] = a3; }
    __syncthreads();

    if (t == 0) {
        ull r0 = wtop[0][0], r1 = wtop[0][1], r2 = wtop[0][2], r3 = wtop[0][3];
#pragma unroll
        for (int w = 1; w < 6; w++)
            merge4(r0, r1, r2, r3, wtop[w][0], wtop[w][1], wtop[w][2], wtop[w][3]);
        ull* c = g_cand + (size_t)(b * NRB + rb) * 4;
        c[0] = r0; c[1] = r1; c[2] = r2; c[3] = r3;
        __threadfence();
        int prev = atomicAdd(&g_cnt[b], 1);
        s_last = (prev == NRB - 1);
    }
    __syncthreads();

    // Last block of this batch: merge all 90*4 = 360 candidates -> output.
    if (s_last) {
        __threadfence();          // acquire: make all g_cand writes visible
        const ull* cand = g_cand + (size_t)b * NRB * 4;
        ull c0 = cand[t], c1 = 0, c2 = 0, c3 = 0;        // t < 360 (192 threads)
        {
            int i2i = t + 192;
            ull x = (i2i < NRB * 4) ? cand[i2i] : 0;
            merge4(c0, c1, c2, c3, x, 0, 0, 0);
        }
#pragma unroll
        for (int s = 16; s > 0; s >>= 1) {
            ull b0 = __shfl_xor_sync(0xFFFFFFFFu, c0, s);
            ull b1 = __shfl_xor_sync(0xFFFFFFFFu, c1, s);
            ull b2 = __shfl_xor_sync(0xFFFFFFFFu, c2, s);
            ull b3 = __shfl_xor_sync(0xFFFFFFFFu, c3, s);
            merge4(c0, c1, c2, c3, b0, b1, b2, b3);
        }
        __syncthreads();          // wtop reuse safe
        if (lane == 0) { wtop[wid][0] = c0; wtop[wid][1] = c1; wtop[wid][2] = c2; wtop[wid][3] = c3; }
        __syncthreads();
        if (t == 0) {
            ull r0 = wtop[0][0], r1 = wtop[0][1], r2 = wtop[0][2], r3 = wtop[0][3];
#pragma unroll
            for (int w = 1; w < 6; w++)
                merge4(r0, r1, r2, r3, wtop[w][0], wtop[w][1], wtop[w][2], wtop[w][3]);
            ull rs[4] = { r0, r1, r2, r3 };
#pragma unroll
            for (int k = 0; k < 4; k++) {
                ull kk = rs[k];
                float v = ord2f((unsigned)(kk >> 32));
                unsigned gi = ~((unsigned)(kk & 0xFFFFFFFFu));
                int m  = (int)(gi % NY);
                int yy = (int)(gi / NY);
                out[b * 4 + k] = v;
                out[32 + (b * 4 + k) * 2 + 0] = (float)(m  - 90);
                out[32 + (b * 4 + k) * 2 + 1] = (float)(yy - 90);
            }
        }
    }
}

// ---------------------------------------------------------------------------
extern "C" void kernel_launch(void* const* d_in, const int* in_sizes, int n_in,
                              void* d_out, int out_size)
{
    // Positional defaults per metadata order: src, rot, ref_fft, gridF
    const float* src = (const float*)d_in[0];   // 8*2*192^3 = 113246208
    const float* rot = (n_in > 1) ? (const float*)d_in[1] : nullptr;  // 72
    const float* ref = (n_in > 2) ? (const float*)d_in[2] : nullptr;  // 262080
    for (int i = 0; i < n_in; i++) {
        switch (in_sizes[i]) {
            case 113246208: src = (const float*)d_in[i]; break;
            case 72:        rot = (const float*)d_in[i]; break;
            case 262080:    ref = (const float*)d_in[i]; break;
            default: break; // gridF unused — recomputed analytically
        }
    }
    float* out = (float*)d_out;

    kA_sample_ifft_y<<<NB * NCB, 192>>>(src, rot, ref);
    kB_c2r_top4_final<<<NB * NRB, 192>>>(out);
}

// round 14
// speedup vs baseline: 2.5100x; 1.1920x over previous
#include <cuda_runtime.h>
#include <cuda_bf16.h>
#include <math_constants.h>

// Problem constants
#define NB 8          // batch
#define NY 180        // RENDER
#define NX 91         // XDIM+1
#define NV 192        // TEMPLATERES
#define SCALE_IN  (32400.0f / 7077888.0f)  // RENDER^2 / TEMPLATERES^3
#define SCALE_OUT (2.0f / 32400.0f)        // 2 (r_k_val) / 180^2 (irfft2 norm)

#define NRB 180       // kB blocks per batch (1 row each)

typedef unsigned long long ull;

// Scratch (device globals; no allocation allowed)
__device__ float2 g_tmid[NB * NY * NX];    // after column iDFT:  [b][ky][x]
__device__ ull    g_cand[NB * NRB * 4];    // per-block top-4 packed keys
__device__ int    g_cnt[NB];               // last-block counters (reset in kernel A)

// ---- packed key helpers: (orderable float bits << 32) | ~index -------------
__device__ __forceinline__ unsigned f2ord(float v) {
    unsigned u = __float_as_uint(v);
    return (u & 0x80000000u) ? ~u : (u | 0x80000000u);
}
__device__ __forceinline__ float ord2f(unsigned ou) {
    unsigned u = (ou & 0x80000000u) ? (ou ^ 0x80000000u) : ~ou;
    return __uint_as_float(u);
}
__device__ __forceinline__ ull kmax(ull a, ull b) { return a > b ? a : b; }
__device__ __forceinline__ ull kmin(ull a, ull b) { return a < b ? a : b; }

// Branch-free merge of two desc-sorted 4-lists -> top-4 (cold path only).
__device__ __forceinline__ void merge4(ull& a0, ull& a1, ull& a2, ull& a3,
                                       ull b0, ull b1, ull b2, ull b3) {
    ull m0 = kmax(a0, b0);
    ull m1 = kmax(kmax(a1, b1), kmin(a0, b0));
    ull m2 = kmax(kmax(a2, b2), kmax(kmin(a0, b1), kmin(a1, b0)));
    ull m3 = kmax(kmax(a3, b3),
                  kmax(kmin(a1, b1), kmax(kmin(a0, b2), kmin(a2, b0))));
    a0 = m0; a1 = m1; a2 = m2; a3 = m3;
}

// complex rotate: w <- w * s
__device__ __forceinline__ void crot(float2& w, float2 s) {
    float tx = w.x * s.x - w.y * s.y;
    float ty = w.x * s.y + w.y * s.x;
    w.x = tx; w.y = ty;
}

// start twiddle e^{i r theta} for r in 0..3 given w1=e^{i theta}, w2=e^{i 2theta}
__device__ __forceinline__ float2 wstart(int r, float2 w1, float2 w2) {
    if (r == 0) return make_float2(1.0f, 0.0f);
    if (r == 1) return w1;
    if (r == 2) return w2;
    return make_float2(w1.x * w2.x - w1.y * w2.y, w1.x * w2.y + w1.y * w2.x);
}

// ---------------------------------------------------------------------------
// Kernel A: block = (b, one column x). Phase 1: 180 threads sample the
// column's grid points into smem. Phase 2: 4 lanes per output ky (46 groups):
// lane r accumulates the y = r (mod 4) quarter-chain (45 iters, twiddle
// rotation, step e^{i4theta}); butterfly shfl_xor(2) then (1) reconstructs
// even/odd partial sums; lanes 0..3 write outputs {ky, 180-ky, 90+ky, 90-ky}.
// ---------------------------------------------------------------------------
__global__ __launch_bounds__(192) void kA_sample_ifft_y(
    const float* __restrict__ src,
    const float* __restrict__ rot,
    const float* __restrict__ ref)
{
    __shared__ float2 cols[NY];

    int bx = blockIdx.x;          // 0 .. NB*NX-1
    int x  = bx % NX;
    int b  = bx / NX;
    int t  = threadIdx.x;         // 0..191

    if (bx == 0 && t < NB) g_cnt[t] = 0;   // reset counters for kernel B

    // ---- Phase 1: sampling (one point per thread) ----
    if (t < NY) {
        int y = t;
        int g = y + 90; if (g >= 180) g -= 180;         // fftshift pre-map
        float gx = (float)x        * (1.0f / 96.0f);
        float gy = (float)(g - 90) * (1.0f / 96.0f);

        const float* R = rot + b * 9;
        float p0 = gx * R[0] + gy * R[3];
        float p1 = gx * R[1] + gy * R[4];
        float p2 = gx * R[2] + gy * R[5];

        float fx = (p0 + 1.0f) * 0.5f * 191.0f;
        float fy = (p1 + 1.0f) * 0.5f * 191.0f;
        float fz = (p2 + 1.0f) * 0.5f * 191.0f;
        float fx0 = floorf(fx), fy0 = floorf(fy), fz0 = floorf(fz);
        float wx = fx - fx0, wy = fy - fy0, wz = fz - fz0;
        int ix = (int)fx0, iy = (int)fy0, iz = (int)fz0;

        int xc0 = min(max(ix, 0), NV - 1),     xc1 = min(max(ix + 1, 0), NV - 1);
        int yc0 = min(max(iy, 0), NV - 1),     yc1 = min(max(iy + 1, 0), NV - 1);
        int zc0 = min(max(iz, 0), NV - 1),     zc1 = min(max(iz + 1, 0), NV - 1);
        float wx0 = (1.0f - wx) * (((unsigned)ix       < NV) ? 1.0f : 0.0f);
        float wx1 =         wx  * (((unsigned)(ix + 1) < NV) ? 1.0f : 0.0f);
        float wy0 = (1.0f - wy) * (((unsigned)iy       < NV) ? 1.0f : 0.0f);
        float wy1 =         wy  * (((unsigned)(iy + 1) < NV) ? 1.0f : 0.0f);
        float wz0 = (1.0f - wz) * (((unsigned)iz       < NV) ? 1.0f : 0.0f);
        float wz1 =         wz  * (((unsigned)(iz + 1) < NV) ? 1.0f : 0.0f);

        const float* vr = src + (size_t)b * 2 * NV * NV * NV;
        const float* vi = vr + (size_t)NV * NV * NV;

        size_t r00 = ((size_t)zc0 * NV + yc0) * NV;
        size_t r01 = ((size_t)zc0 * NV + yc1) * NV;
        size_t r10 = ((size_t)zc1 * NV + yc0) * NV;
        size_t r11 = ((size_t)zc1 * NV + yc1) * NV;

        float w000 = wz0 * wy0 * wx0, w001 = wz0 * wy0 * wx1;
        float w010 = wz0 * wy1 * wx0, w011 = wz0 * wy1 * wx1;
        float w100 = wz1 * wy0 * wx0, w101 = wz1 * wy0 * wx1;
        float w110 = wz1 * wy1 * wx0, w111 = wz1 * wy1 * wx1;

        float a000 = __ldg(vr + r00 + xc0), a001 = __ldg(vr + r00 + xc1);
        float a010 = __ldg(vr + r01 + xc0), a011 = __ldg(vr + r01 + xc1);
        float a100 = __ldg(vr + r10 + xc0), a101 = __ldg(vr + r10 + xc1);
        float a110 = __ldg(vr + r11 + xc0), a111 = __ldg(vr + r11 + xc1);
        float b000 = __ldg(vi + r00 + xc0), b001 = __ldg(vi + r00 + xc1);
        float b010 = __ldg(vi + r01 + xc0), b011 = __ldg(vi + r01 + xc1);
        float b100 = __ldg(vi + r10 + xc0), b101 = __ldg(vi + r10 + xc1);
        float b110 = __ldg(vi + r11 + xc0), b111 = __ldg(vi + r11 + xc1);

        float re = w000 * a000 + w001 * a001 + w010 * a010 + w011 * a011
                 + w100 * a100 + w101 * a101 + w110 * a110 + w111 * a111;
        float im = w000 * b000 + w001 * b001 + w010 * b010 + w011 * b011
                 + w100 * b100 + w101 * b101 + w110 * b110 + w111 * b111;
        re *= SCALE_IN;
        im *= SCALE_IN;

        const float* rp = ref + ((size_t)(b * NY + t) * NX + x) * 2;
        float rr = rp[0], ri = rp[1];
        cols[t] = make_float2(re * rr + im * ri, im * rr - re * ri);
    }
    __syncthreads();

    // ---- Phase 2: iDFT along y, quarter-chains ----
    int ky = t >> 2;
    int r  = t & 3;
    bool active = (ky < 46);

    float AX = 0, AY = 0, BX = 0, BY = 0;   // cos / sin partial sums (residue r)
    if (active) {
        float s1, c1;
        sincospif((float)ky * (1.0f / 90.0f), &s1, &c1);   // theta = 2*pi*ky/180
        float2 w1 = make_float2(c1, s1);
        float2 w2 = make_float2(c1 * c1 - s1 * s1, 2.0f * c1 * s1);
        float2 w4 = make_float2(w2.x * w2.x - w2.y * w2.y, 2.0f * w2.x * w2.y);
        float2 w  = wstart(r, w1, w2);
        for (int y = r; y < NY; y += 4) {
            float2 v = cols[y];
            AX += v.x * w.x; AY += v.y * w.x;
            BX += v.x * w.y; BY += v.y * w.y;
            crot(w, w4);
        }
    }
    // butterfly (unconditional): xor 2 -> even/odd sums, xor 1 -> exchange
    AX += __shfl_xor_sync(0xFFFFFFFFu, AX, 2);
    AY += __shfl_xor_sync(0xFFFFFFFFu, AY, 2);
    BX += __shfl_xor_sync(0xFFFFFFFFu, BX, 2);
    BY += __shfl_xor_sync(0xFFFFFFFFu, BY, 2);
    float oAX = __shfl_xor_sync(0xFFFFFFFFu, AX, 1);
    float oAY = __shfl_xor_sync(0xFFFFFFFFu, AY, 1);
    float oBX = __shfl_xor_sync(0xFFFFFFFFu, BX, 1);
    float oBY = __shfl_xor_sync(0xFFFFFFFFu, BY, 1);

    if (active) {
        bool ev = ((r & 1) == 0);
        float AXe = ev ? AX : oAX, AXo = ev ? oAX : AX;
        float AYe = ev ? AY : oAY, AYo = ev ? oAY : AY;
        float BXe = ev ? BX : oBX, BXo = ev ? oBX : BX;
        float BYe = ev ? BY : oBY, BYo = ev ? oBY : BY;

        float2* base = g_tmid + (size_t)b * NY * NX + x;
        if (r == 0) {
            float SX = AXe + AXo, SY = AYe + AYo, TX = BXe + BXo, TY = BYe + BYo;
            base[(size_t)ky * NX] = make_float2(SX - TY, TX + SY);              // out[ky]
        } else if (r == 1) {
            float SX = AXe + AXo, SY = AYe + AYo, TX = BXe + BXo, TY = BYe + BYo;
            base[(size_t)((NY - ky) % NY) * NX] = make_float2(SX + TY, SY - TX); // out[180-ky]
        } else if (r == 2 && ky != 45) {
            float DX = AXe - AXo, DY = AYe - AYo, EX = BXe - BXo, EY = BYe - BYo;
            base[(size_t)(90 + ky) * NX] = make_float2(DX - EY, EX + DY);        // out[90+ky]
        } else if (r == 3 && ky != 45) {
            float DX = AXe - AXo, DY = AYe - AYo, EX = BXe - BXo, EY = BYe - BYo;
            base[(size_t)(90 - ky) * NX] = make_float2(DX + EY, DY - EX);        // out[90-ky]
        }
    }
}

// ---------------------------------------------------------------------------
// Kernel B: block = (b, one row ky). c2r inverse DFT along x (91 -> 180):
// 4 lanes per output m (46 groups), lane r covers k = r (mod 4) quarter-chain
// (~23 iters); butterfly shfl_xor(2,1); lanes emit candidates for
// {m, 180-m, 90+m, 90-m} (duplicates dropped). Warp + block top-4 via REDUX
// (__reduce_max/min_sync). LAST block per batch merges 180*4 = 720 keys.
// Output layout: [0,32) r_k_val (8,4); [32,96) trans (8,4,2).
// ---------------------------------------------------------------------------
__global__ __launch_bounds__(192) void kB_c2r_top4_final(float* __restrict__ out)
{
    __shared__ float2 rows[NX];
    __shared__ ull    wtop[6][4];
    __shared__ int    s_last;

    int bx = blockIdx.x;          // 0 .. NB*NRB-1
    int ky = bx % NRB;
    int b  = bx / NRB;
    int t  = threadIdx.x;         // 0..191

    if (t < NX) rows[t] = g_tmid[(size_t)(b * NY + ky) * NX + t];
    __syncthreads();

    int m = t >> 2;
    int r = t & 3;
    bool active = (m < 46);

    float A = 0, B = 0;           // A = sum ar*cos(k theta), B = sum ai*sin(k theta)
    if (active) {
        float s1, c1;
        sincospif((float)m * (1.0f / 90.0f), &s1, &c1);    // theta = 2*pi*m/180
        float2 w1 = make_float2(c1, s1);
        float2 w2 = make_float2(c1 * c1 - s1 * s1, 2.0f * c1 * s1);
        float2 w4 = make_float2(w2.x * w2.x - w2.y * w2.y, 2.0f * w2.x * w2.y);
        float2 w;
        int k0;
        if (r == 0)      { w = w4; k0 = 4; }               // k = 4, 8, ..., 88
        else if (r == 1) { w = w1; k0 = 1; }               // k = 1, 5, ..., 89
        else if (r == 2) { w = w2; k0 = 2; }               // k = 2, 6, ..., 86
        else             { w = wstart(3, w1, w2); k0 = 3; } // k = 3, 7, ..., 87
        for (int k = k0; k < 90; k += 4) {
            float2 cv = rows[k];
            A += cv.x * w.x; B += cv.y * w.y;
            crot(w, w4);
        }
    }
    // butterfly (unconditional)
    A += __shfl_xor_sync(0xFFFFFFFFu, A, 2);
    B += __shfl_xor_sync(0xFFFFFFFFu, B, 2);
    float oA = __shfl_xor_sync(0xFFFFFFFFu, A, 1);
    float oB = __shfl_xor_sync(0xFFFFFFFFu, B, 1);

    unsigned myv = 0, myi = 0xFFFFFFFFu;   // candidate (ord value, index)
    if (active) {
        bool ev = ((r & 1) == 0);
        float Ae = ev ? A : oA, Ao = ev ? oA : A;
        float Be = ev ? B : oB, Bo = ev ? oB : B;
        float base = rows[0].x + ((m & 1) ? -rows[90].x : rows[90].x);

        float val; unsigned gi; bool emit = true;
        unsigned gb = (unsigned)(ky * NY);
        if (r == 0) {
            val = base + 2.0f * ((Ae - Be) + (Ao - Bo));   // r[m]
            gi = gb + (unsigned)m;
        } else if (r == 1) {
            val = base + 2.0f * ((Ae + Be) + (Ao + Bo));   // r[180-m]
            gi = gb + (unsigned)((NY - m) % NY);
            emit = (m != 0);
        } else if (r == 2) {
            val = base + 2.0f * ((Ae - Be) - (Ao - Bo));   // r[90+m]
            gi = gb + (unsigned)(90 + m);
            emit = (m != 45);
        } else {
            val = base + 2.0f * ((Ae + Be) - (Ao + Bo));   // r[90-m]
            gi = gb + (unsigned)(90 - m);
            emit = (m != 0 && m != 45);
        }
        if (emit) { myv = f2ord(val * SCALE_OUT); myi = gi; }
    }

    // ---- warp top-4 via REDUX (4 pop iterations; all lanes participate) ----
    ull wk0, wk1, wk2, wk3;
    {
        unsigned v = myv, idx = myi;
#define TOP_ITER(DST)                                                       \
        {                                                                   \
            unsigned mv = __reduce_max_sync(0xFFFFFFFFu, v);                \
            unsigned ci = (v == mv) ? idx : 0xFFFFFFFFu;                    \
            unsigned mi = __reduce_min_sync(0xFFFFFFFFu, ci);               \
            if (v == mv && idx == mi) { v = 0; idx = 0xFFFFFFFFu; }         \
            DST = ((ull)mv << 32) | (unsigned)(~mi);                        \
        }
        TOP_ITER(wk0) TOP_ITER(wk1) TOP_ITER(wk2) TOP_ITER(wk3)
    }
    int wid = t >> 5, lane = t & 31;
    if (lane == 0) { wtop[wid][0] = wk0; wtop[wid][1] = wk1; wtop[wid][2] = wk2; wtop[wid][3] = wk3; }
    __syncthreads();

    // ---- block top-4: one warp reduces the 24 warp keys ----
    if (t < 32) {
        unsigned v = 0, idx = 0xFFFFFFFFu;
        if (t < 24) {
            ull kk = (&wtop[0][0])[t];
            v = (unsigned)(kk >> 32);
            idx = ~((unsigned)(kk & 0xFFFFFFFFu));
        }
        ull bk0, bk1, bk2, bk3;
        {
            unsigned vv = v, ii = idx;
#define TOPB_ITER(DST)                                                      \
            {                                                               \
                unsigned mv = __reduce_max_sync(0xFFFFFFFFu, vv);           \
                unsigned ci = (vv == mv) ? ii : 0xFFFFFFFFu;                \
                unsigned mi = __reduce_min_sync(0xFFFFFFFFu, ci);           \
                if (vv == mv && ii == mi) { vv = 0; ii = 0xFFFFFFFFu; }     \
                DST = ((ull)mv << 32) | (unsigned)(~mi);                    \
            }
            TOPB_ITER(bk0) TOPB_ITER(bk1) TOPB_ITER(bk2) TOPB_ITER(bk3)
        }
        if (t == 0) {
            ull* c = g_cand + (size_t)(b * NRB + ky) * 4;
            c[0] = bk0; c[1] = bk1; c[2] = bk2; c[3] = bk3;
            __threadfence();
            int prev = atomicAdd(&g_cnt[b], 1);
            s_last = (prev == NRB - 1);
        }
    }
    __syncthreads();

    // ---- last block of this batch: merge all 180*4 = 720 candidates ----
    if (s_last) {
        __threadfence();          // acquire: make all g_cand writes visible
        const ull* cand = g_cand + (size_t)b * NRB * 4;
        ull c0 = 0, c1 = 0, c2 = 0, c3 = 0;
#pragma unroll
        for (int j = 0; j < 4; j++) {
            int i = t + j * 192;
            ull xk = (i < NRB * 4) ? cand[i] : 0;
            merge4(c0, c1, c2, c3, xk, 0, 0, 0);
        }
#pragma unroll
        for (int s = 16; s > 0; s >>= 1) {
            ull b0 = __shfl_xor_sync(0xFFFFFFFFu, c0, s);
            ull b1 = __shfl_xor_sync(0xFFFFFFFFu, c1, s);
            ull b2 = __shfl_xor_sync(0xFFFFFFFFu, c2, s);
            ull b3 = __shfl_xor_sync(0xFFFFFFFFu, c3, s);
            merge4(c0, c1, c2, c3, b0, b1, b2, b3);
        }
        __syncthreads();          // wtop reuse safe
        if (lane == 0) { wtop[wid][0] = c0; wtop[wid][1] = c1; wtop[wid][2] = c2; wtop[wid][3] = c3; }
        __syncthreads();
        if (t == 0) {
            ull r0 = wtop[0][0], r1 = wtop[0][1], r2 = wtop[0][2], r3 = wtop[0][3];
#pragma unroll
            for (int w = 1; w < 6; w++)
                merge4(r0, r1, r2, r3, wtop[w][0], wtop[w][1], wtop[w][2], wtop[w][3]);
            ull rs[4] = { r0, r1, r2, r3 };
#pragma unroll
            for (int k = 0; k < 4; k++) {
                ull kk = rs[k];
                float v = ord2f((unsigned)(kk >> 32));
                unsigned gi = ~((unsigned)(kk & 0xFFFFFFFFu));
                int mm = (int)(gi % NY);
                int yy = (int)(gi / NY);
                out[b * 4 + k] = v;
                out[32 + (b * 4 + k) * 2 + 0] = (float)(mm - 90);
                out[32 + (b * 4 + k) * 2 + 1] = (float)(yy - 90);
            }
        }
    }
}

// ---------------------------------------------------------------------------
extern "C" void kernel_launch(void* const* d_in, const int* in_sizes, int n_in,
                              void* d_out, int out_size)
{
    // Positional defaults per metadata order: src, rot, ref_fft, gridF
    const float* src = (const float*)d_in[0];   // 8*2*192^3 = 113246208
    const float* rot = (n_in > 1) ? (const float*)d_in[1] : nullptr;  // 72
    const float* ref = (n_in > 2) ? (const float*)d_in[2] : nullptr;  // 262080
    for (int i = 0; i < n_in; i++) {
        switch (in_sizes[i]) {
            case 113246208: src = (const float*)d_in[i]; break;
            case 72:        rot = (const float*)d_in[i]; break;
            case 262080:    ref = (const float*)d_in[i]; break;
            default: break; // gridF unused — recomputed analytically
        }
    }
    float* out = (float*)d_out;

    kA_sample_ifft_y<<<NB * NX, 192>>>(src, rot, ref);
    kB_c2r_top4_final<<<NB * NRB, 192>>>(out);
}